// round 1
// baseline (speedup 1.0000x reference)
#include <cuda_runtime.h>
#include <math.h>

// ---------------------------------------------------------------------------
// NCC3D: z[8,1,8,8,8] template, x[8,1,128,128,128] search -> out[8,1,121,121,121]
// Pipeline:
//   k_template : per-batch zero-mean template (g_zc) + L2 norm (g_zn)
//   k_wsum     : sliding 8-window sums along W of x and x^2  -> g_s1/g_s2 [8,128,128,121]
//   k_hsum     : window sums along H                          -> g_t1/g_t2 [8,128,121,121]
//   k_dsum     : window sums along D + denominator inverse    -> g_dinv   [8,121,121,121]
//   k_cross    : direct correlation with zc (f32x2 packed FMA), * g_dinv  -> out
// ---------------------------------------------------------------------------

#define NB 8
#define NW 128
#define NO 121

static const size_t N_S = (size_t)NB * 128 * 128 * 121;   // 15,859,712
static const size_t N_T = (size_t)NB * 128 * 121 * 121;   // 14,992,384
static const size_t N_O = (size_t)NB * 121 * 121 * 121;   // 14,172,488

__device__ float g_zc[NB * 512];
__device__ float g_zn[NB];
__device__ float g_s1[(size_t)NB * 128 * 128 * 121];
__device__ float g_s2[(size_t)NB * 128 * 128 * 121];
__device__ float g_t1[(size_t)NB * 128 * 121 * 121];
__device__ float g_t2[(size_t)NB * 128 * 121 * 121];
__device__ float g_dinv[(size_t)NB * 121 * 121 * 121];

// ---------------- packed f32x2 helpers ----------------
__device__ __forceinline__ void fma2(unsigned long long& a,
                                     unsigned long long x,
                                     unsigned long long z) {
    asm("fma.rn.f32x2 %0, %1, %2, %0;" : "+l"(a) : "l"(x), "l"(z));
}
__device__ __forceinline__ float2 u2f(unsigned long long u) {
    float2 f;
    asm("mov.b64 {%0, %1}, %2;" : "=f"(f.x), "=f"(f.y) : "l"(u));
    return f;
}

// ---------------- template stats ----------------
__global__ void ncc_k_template(const float* __restrict__ z) {
    __shared__ float red[512];
    int b = blockIdx.x, t = threadIdx.x;
    float v = z[b * 512 + t];
    red[t] = v;
    __syncthreads();
    for (int s = 256; s > 0; s >>= 1) {
        if (t < s) red[t] += red[t + s];
        __syncthreads();
    }
    float mean = red[0] * (1.0f / 512.0f);
    __syncthreads();
    float c = v - mean;
    g_zc[b * 512 + t] = c;
    red[t] = c * c;
    __syncthreads();
    for (int s = 256; s > 0; s >>= 1) {
        if (t < s) red[t] += red[t + s];
        __syncthreads();
    }
    if (t == 0) g_zn[b] = sqrtf(red[0]);
}

// ---------------- W-pass window sums ----------------
__global__ void ncc_k_wsum(const float* __restrict__ x) {
    int row = blockIdx.x;          // (b*128+d)*128+h, 0..131071
    int t = threadIdx.x;           // 0..127
    __shared__ float r[128];
    r[t] = x[(size_t)row * 128 + t];
    __syncthreads();
    if (t < 121) {
        float s = 0.f, s2 = 0.f;
#pragma unroll
        for (int k = 0; k < 8; k++) {
            float v = r[t + k];
            s += v;
            s2 += v * v;
        }
        size_t o = (size_t)row * 121 + t;
        g_s1[o] = s;
        g_s2[o] = s2;
    }
}

// ---------------- H-pass window sums ----------------
__global__ void ncc_k_hsum() {
    int bd = blockIdx.x;           // 0..1023 = b*128+d
    int w = threadIdx.x;
    if (w >= 121) return;
    int ho0 = blockIdx.y * 16;
    const float* s1 = g_s1 + (size_t)bd * 128 * 121 + w;
    const float* s2 = g_s2 + (size_t)bd * 128 * 121 + w;
    for (int j = 0; j < 16; j++) {
        int ho = ho0 + j;
        if (ho >= 121) break;
        float a = 0.f, c = 0.f;
#pragma unroll
        for (int k = 0; k < 8; k++) {
            a += s1[(size_t)(ho + k) * 121];
            c += s2[(size_t)(ho + k) * 121];
        }
        size_t o = ((size_t)bd * 121 + ho) * 121 + w;
        g_t1[o] = a;
        g_t2[o] = c;
    }
}

// ---------------- D-pass + denominator inverse ----------------
__global__ void ncc_k_dsum() {
    int b = blockIdx.z;
    int p = blockIdx.x * 256 + threadIdx.x;
    if (p >= 121 * 121) return;
    int h = p / 121;
    int w = p - h * 121;
    float zn = g_zn[b];
    int d0 = blockIdx.y * 16;
    int d1 = min(121, d0 + 16);
    for (int d = d0; d < d1; d++) {
        float a = 0.f, c = 0.f;
#pragma unroll
        for (int k = 0; k < 8; k++) {
            size_t idx = (((size_t)(b * 128 + d + k)) * 121 + h) * 121 + w;
            a += g_t1[idx];
            c += g_t2[idx];
        }
        float var = fmaxf(c - a * a * (1.0f / 512.0f), 0.0f);
        float den = sqrtf(var + 1e-12f) * zn + 1e-5f;
        g_dinv[(((size_t)(b * 121 + d)) * 121 + h) * 121 + w] = 1.0f / den;
    }
}

// ---------------- cross-correlation (compute-bound) ----------------
// Block: 256 threads. Output tile 4(d) x 4(h) x 128(w, 121 valid).
// Shared x tile: [11][11][144] floats (w padded+zeroed) + 512 z-pairs.
#define TSH 144
#define TSD (11 * 144)
#define TILE_ELEMS (11 * TSD)
#define SMEM_BYTES ((TILE_ELEMS + 1024) * 4)

__global__ void __launch_bounds__(256) ncc_k_cross(const float* __restrict__ x,
                                                   float* __restrict__ out) {
    extern __shared__ float smem[];
    float* tile = smem;
    float2* zp = (float2*)(smem + TILE_ELEMS);

    int b = blockIdx.z;
    int d0 = blockIdx.x * 4, h0 = blockIdx.y * 4;
    int tid = threadIdx.x;

    const float* xb = x + (size_t)b * 128 * 128 * 128;
    for (int i = tid; i < TILE_ELEMS; i += 256) {
        int dd = i / TSD;
        int rem = i - dd * TSD;
        int hh = rem / TSH;
        int w = rem - hh * TSH;
        float v = 0.f;
        if (w < 128) {
            int gd = min(d0 + dd, 127);
            int gh = min(h0 + hh, 127);
            v = xb[((size_t)(gd * 128 + gh)) * 128 + w];
        }
        tile[i] = v;
    }
    for (int t = tid; t < 512; t += 256) {
        float zv = g_zc[b * 512 + t];
        zp[t] = make_float2(zv, zv);
    }
    __syncthreads();

    int pr = tid >> 4;
    int od = pr >> 2, oh = pr & 3;
    int wt = tid & 15;
    int wb = wt * 8;

    unsigned long long A[4] = {0ull, 0ull, 0ull, 0ull};   // even-kw, outputs (2p,2p+1)
    unsigned long long Bv[5] = {0ull, 0ull, 0ull, 0ull, 0ull}; // odd-kw, outputs (2i-1,2i)

    const float* tb = tile + od * TSD + oh * TSH + wb;
    const unsigned long long* zb = (const unsigned long long*)zp;

#pragma unroll 1
    for (int kd = 0; kd < 8; kd++) {
        const float* rb = tb + kd * TSD;
        const unsigned long long* zr0 = zb + kd * 64;
#pragma unroll
        for (int kh = 0; kh < 8; kh++) {
            const ulonglong2* r = (const ulonglong2*)(rb + kh * TSH);
            ulonglong2 q0 = r[0], q1 = r[1], q2 = r[2], q3 = r[3];
            unsigned long long pe[8] = {q0.x, q0.y, q1.x, q1.y,
                                        q2.x, q2.y, q3.x, q3.y};
            const unsigned long long* zr = zr0 + kh * 8;
#pragma unroll
            for (int e = 0; e < 4; e++) {          // kw = 0,2,4,6
                unsigned long long z2 = zr[2 * e];
#pragma unroll
                for (int p = 0; p < 4; p++) fma2(A[p], pe[p + e], z2);
            }
#pragma unroll
            for (int o = 1; o <= 4; o++) {         // kw = 1,3,5,7
                unsigned long long z2 = zr[2 * o - 1];
#pragma unroll
                for (int i2 = 0; i2 < 5; i2++) fma2(Bv[i2], pe[i2 + o - 1], z2);
            }
        }
    }

    int d = d0 + od, h = h0 + oh;
    if (d < 121 && h < 121) {
        float res[8];
#pragma unroll
        for (int p = 0; p < 4; p++) {
            float2 ea = u2f(A[p]);
            float2 b0 = u2f(Bv[p]);
            float2 b1 = u2f(Bv[p + 1]);
            res[2 * p] = ea.x + b0.y;
            res[2 * p + 1] = ea.y + b1.x;
        }
        size_t base = (((size_t)(b * 121 + d)) * 121 + h) * 121;
#pragma unroll
        for (int j = 0; j < 8; j++) {
            int w = wb + j;
            if (w < 121) {
                size_t idx = base + w;
                out[idx] = res[j] * __ldg(&g_dinv[idx]);
            }
        }
    }
}

// ---------------------------------------------------------------------------
extern "C" void kernel_launch(void* const* d_in, const int* in_sizes, int n_in,
                              void* d_out, int out_size) {
    (void)n_in;
    (void)out_size;
    const float* z = (const float*)d_in[0];
    const float* x = (const float*)d_in[1];
    if (in_sizes[0] != NB * 512) {  // guard against input-order ambiguity
        z = (const float*)d_in[1];
        x = (const float*)d_in[0];
    }
    float* out = (float*)d_out;

    cudaFuncSetAttribute(ncc_k_cross,
                         cudaFuncAttributeMaxDynamicSharedMemorySize,
                         SMEM_BYTES);

    ncc_k_template<<<NB, 512>>>(z);
    ncc_k_wsum<<<NB * 128 * 128, 128>>>(x);
    ncc_k_hsum<<<dim3(NB * 128, 8), 128>>>();
    ncc_k_dsum<<<dim3(58, 8, NB), 256>>>();
    ncc_k_cross<<<dim3(31, 31, NB), 256, SMEM_BYTES>>>(x, out);
}

// round 2
// speedup vs baseline: 1.0005x; 1.0005x over previous
#include <cuda_runtime.h>
#include <math.h>

// ---------------------------------------------------------------------------
// NCC3D: z[8,1,8,8,8] template, x[8,1,128,128,128] search -> out[8,1,121,121,121]
// Pipeline:
//   k_template : per-batch zero-mean template (g_zc) + L2 norm (g_zn)
//   k_wsum     : sliding 8-window sums along W of x and x^2  -> g_s1/g_s2 [8,128,128,121]
//   k_hsum     : window sums along H                          -> g_t1/g_t2 [8,128,121,121]
//   k_dsum     : window sums along D + denominator inverse    -> g_dinv   [8,121,121,121]
//   k_cross    : direct correlation with zc (f32x2 packed FMA), * g_dinv  -> out
// ---------------------------------------------------------------------------

#define NB 8
#define NW 128
#define NO 121

static const size_t N_S = (size_t)NB * 128 * 128 * 121;   // 15,859,712
static const size_t N_T = (size_t)NB * 128 * 121 * 121;   // 14,992,384
static const size_t N_O = (size_t)NB * 121 * 121 * 121;   // 14,172,488

__device__ float g_zc[NB * 512];
__device__ float g_zn[NB];
__device__ float g_s1[(size_t)NB * 128 * 128 * 121];
__device__ float g_s2[(size_t)NB * 128 * 128 * 121];
__device__ float g_t1[(size_t)NB * 128 * 121 * 121];
__device__ float g_t2[(size_t)NB * 128 * 121 * 121];
__device__ float g_dinv[(size_t)NB * 121 * 121 * 121];

// ---------------- packed f32x2 helpers ----------------
__device__ __forceinline__ void fma2(unsigned long long& a,
                                     unsigned long long x,
                                     unsigned long long z) {
    asm("fma.rn.f32x2 %0, %1, %2, %0;" : "+l"(a) : "l"(x), "l"(z));
}
__device__ __forceinline__ float2 u2f(unsigned long long u) {
    float2 f;
    asm("mov.b64 {%0, %1}, %2;" : "=f"(f.x), "=f"(f.y) : "l"(u));
    return f;
}

// ---------------- template stats ----------------
__global__ void ncc_k_template(const float* __restrict__ z) {
    __shared__ float red[512];
    int b = blockIdx.x, t = threadIdx.x;
    float v = z[b * 512 + t];
    red[t] = v;
    __syncthreads();
    for (int s = 256; s > 0; s >>= 1) {
        if (t < s) red[t] += red[t + s];
        __syncthreads();
    }
    float mean = red[0] * (1.0f / 512.0f);
    __syncthreads();
    float c = v - mean;
    g_zc[b * 512 + t] = c;
    red[t] = c * c;
    __syncthreads();
    for (int s = 256; s > 0; s >>= 1) {
        if (t < s) red[t] += red[t + s];
        __syncthreads();
    }
    if (t == 0) g_zn[b] = sqrtf(red[0]);
}

// ---------------- W-pass window sums ----------------
__global__ void ncc_k_wsum(const float* __restrict__ x) {
    int row = blockIdx.x;          // (b*128+d)*128+h, 0..131071
    int t = threadIdx.x;           // 0..127
    __shared__ float r[128];
    r[t] = x[(size_t)row * 128 + t];
    __syncthreads();
    if (t < 121) {
        float s = 0.f, s2 = 0.f;
#pragma unroll
        for (int k = 0; k < 8; k++) {
            float v = r[t + k];
            s += v;
            s2 += v * v;
        }
        size_t o = (size_t)row * 121 + t;
        g_s1[o] = s;
        g_s2[o] = s2;
    }
}

// ---------------- H-pass window sums ----------------
__global__ void ncc_k_hsum() {
    int bd = blockIdx.x;           // 0..1023 = b*128+d
    int w = threadIdx.x;
    if (w >= 121) return;
    int ho0 = blockIdx.y * 16;
    const float* s1 = g_s1 + (size_t)bd * 128 * 121 + w;
    const float* s2 = g_s2 + (size_t)bd * 128 * 121 + w;
    for (int j = 0; j < 16; j++) {
        int ho = ho0 + j;
        if (ho >= 121) break;
        float a = 0.f, c = 0.f;
#pragma unroll
        for (int k = 0; k < 8; k++) {
            a += s1[(size_t)(ho + k) * 121];
            c += s2[(size_t)(ho + k) * 121];
        }
        size_t o = ((size_t)bd * 121 + ho) * 121 + w;
        g_t1[o] = a;
        g_t2[o] = c;
    }
}

// ---------------- D-pass + denominator inverse ----------------
__global__ void ncc_k_dsum() {
    int b = blockIdx.z;
    int p = blockIdx.x * 256 + threadIdx.x;
    if (p >= 121 * 121) return;
    int h = p / 121;
    int w = p - h * 121;
    float zn = g_zn[b];
    int d0 = blockIdx.y * 16;
    int d1 = min(121, d0 + 16);
    for (int d = d0; d < d1; d++) {
        float a = 0.f, c = 0.f;
#pragma unroll
        for (int k = 0; k < 8; k++) {
            size_t idx = (((size_t)(b * 128 + d + k)) * 121 + h) * 121 + w;
            a += g_t1[idx];
            c += g_t2[idx];
        }
        float var = fmaxf(c - a * a * (1.0f / 512.0f), 0.0f);
        float den = sqrtf(var + 1e-12f) * zn + 1e-5f;
        g_dinv[(((size_t)(b * 121 + d)) * 121 + h) * 121 + w] = 1.0f / den;
    }
}

// ---------------- cross-correlation (compute-bound) ----------------
// Block: 256 threads. Output tile 4(d) x 4(h) x 128(w, 121 valid).
// Shared x tile: [11][11][144] floats (w padded+zeroed) + 512 z-pairs.
#define TSH 144
#define TSD (11 * 144)
#define TILE_ELEMS (11 * TSD)
#define SMEM_BYTES ((TILE_ELEMS + 1024) * 4)

__global__ void __launch_bounds__(256) ncc_k_cross(const float* __restrict__ x,
                                                   float* __restrict__ out) {
    extern __shared__ float smem[];
    float* tile = smem;
    float2* zp = (float2*)(smem + TILE_ELEMS);

    int b = blockIdx.z;
    int d0 = blockIdx.x * 4, h0 = blockIdx.y * 4;
    int tid = threadIdx.x;

    const float* xb = x + (size_t)b * 128 * 128 * 128;
    for (int i = tid; i < TILE_ELEMS; i += 256) {
        int dd = i / TSD;
        int rem = i - dd * TSD;
        int hh = rem / TSH;
        int w = rem - hh * TSH;
        float v = 0.f;
        if (w < 128) {
            int gd = min(d0 + dd, 127);
            int gh = min(h0 + hh, 127);
            v = xb[((size_t)(gd * 128 + gh)) * 128 + w];
        }
        tile[i] = v;
    }
    for (int t = tid; t < 512; t += 256) {
        float zv = g_zc[b * 512 + t];
        zp[t] = make_float2(zv, zv);
    }
    __syncthreads();

    int pr = tid >> 4;
    int od = pr >> 2, oh = pr & 3;
    int wt = tid & 15;
    int wb = wt * 8;

    unsigned long long A[4] = {0ull, 0ull, 0ull, 0ull};   // even-kw, outputs (2p,2p+1)
    unsigned long long Bv[5] = {0ull, 0ull, 0ull, 0ull, 0ull}; // odd-kw, outputs (2i-1,2i)

    const float* tb = tile + od * TSD + oh * TSH + wb;
    const unsigned long long* zb = (const unsigned long long*)zp;

#pragma unroll 1
    for (int kd = 0; kd < 8; kd++) {
        const float* rb = tb + kd * TSD;
        const unsigned long long* zr0 = zb + kd * 64;
#pragma unroll
        for (int kh = 0; kh < 8; kh++) {
            const ulonglong2* r = (const ulonglong2*)(rb + kh * TSH);
            ulonglong2 q0 = r[0], q1 = r[1], q2 = r[2], q3 = r[3];
            unsigned long long pe[8] = {q0.x, q0.y, q1.x, q1.y,
                                        q2.x, q2.y, q3.x, q3.y};
            const unsigned long long* zr = zr0 + kh * 8;
#pragma unroll
            for (int e = 0; e < 4; e++) {          // kw = 0,2,4,6
                unsigned long long z2 = zr[2 * e];
#pragma unroll
                for (int p = 0; p < 4; p++) fma2(A[p], pe[p + e], z2);
            }
#pragma unroll
            for (int o = 1; o <= 4; o++) {         // kw = 1,3,5,7
                unsigned long long z2 = zr[2 * o - 1];
#pragma unroll
                for (int i2 = 0; i2 < 5; i2++) fma2(Bv[i2], pe[i2 + o - 1], z2);
            }
        }
    }

    int d = d0 + od, h = h0 + oh;
    if (d < 121 && h < 121) {
        float res[8];
#pragma unroll
        for (int p = 0; p < 4; p++) {
            float2 ea = u2f(A[p]);
            float2 b0 = u2f(Bv[p]);
            float2 b1 = u2f(Bv[p + 1]);
            res[2 * p] = ea.x + b0.y;
            res[2 * p + 1] = ea.y + b1.x;
        }
        size_t base = (((size_t)(b * 121 + d)) * 121 + h) * 121;
#pragma unroll
        for (int j = 0; j < 8; j++) {
            int w = wb + j;
            if (w < 121) {
                size_t idx = base + w;
                out[idx] = res[j] * __ldg(&g_dinv[idx]);
            }
        }
    }
}

// ---------------------------------------------------------------------------
extern "C" void kernel_launch(void* const* d_in, const int* in_sizes, int n_in,
                              void* d_out, int out_size) {
    (void)n_in;
    (void)out_size;
    const float* z = (const float*)d_in[0];
    const float* x = (const float*)d_in[1];
    if (in_sizes[0] != NB * 512) {  // guard against input-order ambiguity
        z = (const float*)d_in[1];
        x = (const float*)d_in[0];
    }
    float* out = (float*)d_out;

    cudaFuncSetAttribute(ncc_k_cross,
                         cudaFuncAttributeMaxDynamicSharedMemorySize,
                         SMEM_BYTES);

    ncc_k_template<<<NB, 512>>>(z);
    ncc_k_wsum<<<NB * 128 * 128, 128>>>(x);
    ncc_k_hsum<<<dim3(NB * 128, 8), 128>>>();
    ncc_k_dsum<<<dim3(58, 8, NB), 256>>>();
    ncc_k_cross<<<dim3(31, 31, NB), 256, SMEM_BYTES>>>(x, out);
}

// round 5
// speedup vs baseline: 1.0270x; 1.0265x over previous
#include <cuda_runtime.h>
#include <math.h>

// ---------------------------------------------------------------------------
// NCC3D: z[8,1,8,8,8], x[8,1,128,128,128] -> out[8,1,121,121,121]
//   k_template : zero-mean template + L2 norm
//   k_whsum    : fused W+H window sums of x, x^2 (smem-resident per (b,d) slice)
//   k_dsum2    : rolling D window sums + denominator inverse -> g_dinv
//   k_cross    : direct correlation, f32x2 packed FMA, swizzled conflict-free
//                smem tile, 16w x 2h register tile per thread
// ---------------------------------------------------------------------------

#define NB 8

__device__ float g_zc[NB * 512];
__device__ float g_zn[NB];
__device__ float g_t1[(size_t)NB * 128 * 121 * 121];
__device__ float g_t2[(size_t)NB * 128 * 121 * 121];
__device__ float g_dinv[(size_t)NB * 121 * 121 * 121];

// ---------------- packed f32x2 helpers ----------------
__device__ __forceinline__ void fma2(unsigned long long& a,
                                     unsigned long long x,
                                     unsigned long long z) {
    asm("fma.rn.f32x2 %0, %1, %2, %0;" : "+l"(a) : "l"(x), "l"(z));
}
__device__ __forceinline__ float2 u2f(unsigned long long u) {
    float2 f;
    asm("mov.b64 {%0, %1}, %2;" : "=f"(f.x), "=f"(f.y) : "l"(u));
    return f;
}

// ---------------- template stats ----------------
__global__ void ncc_k_template(const float* __restrict__ z) {
    __shared__ float red[512];
    int b = blockIdx.x, t = threadIdx.x;
    float v = z[b * 512 + t];
    red[t] = v;
    __syncthreads();
    for (int s = 256; s > 0; s >>= 1) {
        if (t < s) red[t] += red[t + s];
        __syncthreads();
    }
    float mean = red[0] * (1.0f / 512.0f);
    __syncthreads();
    float c = v - mean;
    g_zc[b * 512 + t] = c;
    red[t] = c * c;
    __syncthreads();
    for (int s = 256; s > 0; s >>= 1) {
        if (t < s) red[t] += red[t + s];
        __syncthreads();
    }
    if (t == 0) g_zn[b] = sqrtf(red[0]);
}

// ---------------- fused W + H window sums (one (b,d) slice per block) -------
#define WH_SMEM (3 * 16384 * 4)
__global__ void __launch_bounds__(256) ncc_k_whsum(const float* __restrict__ x) {
    extern __shared__ float sm[];
    float* xs = sm;              // [128][128]
    float* s1 = sm + 16384;      // [128][128] (w<121 valid)
    float* s2 = sm + 32768;
    int bd = blockIdx.x, tid = threadIdx.x;
    const float* xp = x + (size_t)bd * 16384;
    for (int i = tid; i < 16384; i += 256) xs[i] = xp[i];
    __syncthreads();
    for (int i = tid; i < 16384; i += 256) {
        int w = i & 127;
        if (w < 121) {
            float a = 0.f, c = 0.f;
#pragma unroll
            for (int k = 0; k < 8; k++) {
                float v = xs[i + k];
                a += v;
                c += v * v;
            }
            s1[i] = a;
            s2[i] = c;
        }
    }
    __syncthreads();
    for (int i = tid; i < 121 * 128; i += 256) {
        int ho = i >> 7, w = i & 127;
        if (w < 121) {
            float a = 0.f, c = 0.f;
#pragma unroll
            for (int k = 0; k < 8; k++) {
                a += s1[i + (k << 7)];
                c += s2[i + (k << 7)];
            }
            size_t o = ((size_t)bd * 121 + ho) * 121 + w;
            g_t1[o] = a;
            g_t2[o] = c;
        }
    }
}

// ---------------- rolling D sums + denominator inverse ----------------------
__global__ void __launch_bounds__(256) ncc_k_dsum2() {
    int p = blockIdx.x * 256 + threadIdx.x;
    if (p >= 14641) return;
    int h = p / 121, w = p - h * 121;
    int b = blockIdx.z;
    const int dst[5] = {0, 31, 61, 91, 121};
    int d0 = dst[blockIdx.y], d1 = dst[blockIdx.y + 1];
    size_t tbase = (((size_t)(b * 128)) * 121 + h) * 121 + w;
    float r1[8], r2[8], s1 = 0.f, s2 = 0.f;
#pragma unroll
    for (int k = 0; k < 8; k++) {
        float a = g_t1[tbase + (size_t)(d0 + k) * 14641];
        float c = g_t2[tbase + (size_t)(d0 + k) * 14641];
        r1[k] = a;
        r2[k] = c;
        s1 += a;
        s2 += c;
    }
    float zn = g_zn[b];
    size_t obase = (((size_t)(b * 121)) * 121 + h) * 121 + w;
    for (int dd = d0; dd < d1; dd += 8) {
#pragma unroll
        for (int j = 0; j < 8; j++) {
            int d = dd + j;
            if (d < d1) {
                float var = fmaxf(s2 - s1 * s1 * (1.0f / 512.0f), 0.0f);
                g_dinv[obase + (size_t)d * 14641] =
                    1.0f / (sqrtf(var + 1e-12f) * zn + 1e-5f);
                if (d + 1 < d1) {
                    float n1 = g_t1[tbase + (size_t)(d + 8) * 14641];
                    float n2 = g_t2[tbase + (size_t)(d + 8) * 14641];
                    s1 += n1 - r1[j];
                    r1[j] = n1;
                    s2 += n2 - r2[j];
                    r2[j] = n2;
                }
            }
        }
    }
}

// ---------------- cross-correlation (FMA-bound) -----------------------------
// Block 256 threads = 8 warps. Output tile: 8(d) x 8(h) x 128(w).
// Thread: 1 od (= warp id), 2 oh, 16 w. Accumulators: even bank A[8]
// (out pairs 2p,2p+1), odd bank B[9] (out pairs 2i-1,2i), per oh.
// Tile rows swizzled by 16B granule: phys = g ^ (g>>3) (involution),
// row stride 152 floats (38 granules, == 6 mod 8) -> conflict-free LDS.128.
#define CTH 15
#define RST 152
#define TILE_F (15 * 15 * 152)
#define CR_SMEM ((TILE_F + 1024) * 4)

__global__ void __launch_bounds__(256) ncc_k_cross(const float* __restrict__ x,
                                                   float* __restrict__ out) {
    extern __shared__ float sm[];
    float* tile = sm;
    unsigned long long* zp = (unsigned long long*)(sm + TILE_F);

    int b = blockIdx.z;
    int d0 = blockIdx.x * 8, h0 = blockIdx.y * 8;
    int tid = threadIdx.x;

    const float* xb = x + (size_t)b * 2097152;
    for (int i = tid; i < TILE_F; i += 256) {
        int row = i / RST;
        int wp = i - row * RST;
        int lg = wp >> 2;
        lg = lg ^ (lg >> 3);                 // inverse == forward (involution)
        int w = (lg << 2) | (wp & 3);
        float v = 0.f;
        if (w < 128) {
            int dd = row / CTH, hh = row - dd * CTH;
            int gd = min(d0 + dd, 127), gh = min(h0 + hh, 127);
            v = xb[((size_t)(gd * 128 + gh)) * 128 + w];
        }
        tile[i] = v;
    }
    for (int t = tid; t < 512; t += 256) {
        float zv = g_zc[b * 512 + t];
        float2 f = make_float2(zv, zv);
        zp[t] = *(unsigned long long*)&f;
    }
    __syncthreads();

    int wt = tid & 7, c = tid >> 3;
    int od = c >> 2, oh0 = (c & 3) * 2;
    int wb = wt * 16;

    int off[6];
#pragma unroll
    for (int q = 0; q < 6; q++) {
        int g = 4 * wt + q;
        off[q] = (g ^ (g >> 3)) << 2;        // float offset of swizzled granule
    }

    unsigned long long A0[8], B0[9], A1[8], B1[9];
#pragma unroll
    for (int p = 0; p < 8; p++) { A0[p] = 0ull; A1[p] = 0ull; }
#pragma unroll
    for (int i2 = 0; i2 < 9; i2++) { B0[i2] = 0ull; B1[i2] = 0ull; }

#pragma unroll 1
    for (int kd = 0; kd < 8; kd++) {
        const float* dbase = tile + (od + kd) * (CTH * RST);
#pragma unroll 2
        for (int kh = 0; kh < 8; kh++) {
            unsigned long long zr[8];
            {
                const ulonglong2* z2 =
                    (const ulonglong2*)(zp + ((kd << 3) + kh) * 8);
                ulonglong2 za = z2[0], zb = z2[1], zc = z2[2], zd = z2[3];
                zr[0] = za.x; zr[1] = za.y; zr[2] = zb.x; zr[3] = zb.y;
                zr[4] = zc.x; zr[5] = zc.y; zr[6] = zd.x; zr[7] = zd.y;
            }
            const float* rp = dbase + (oh0 + kh) * RST;
            // ---- phase 0 (oh = oh0) ----
            {
                unsigned long long pe[12];
#pragma unroll
                for (int q = 0; q < 6; q++) {
                    ulonglong2 v = *(const ulonglong2*)(rp + off[q]);
                    pe[2 * q] = v.x;
                    pe[2 * q + 1] = v.y;
                }
#pragma unroll
                for (int m = 0; m < 4; m++) {
                    unsigned long long ze = zr[2 * m];
#pragma unroll
                    for (int p = 0; p < 8; p++) fma2(A0[p], pe[p + m], ze);
                }
#pragma unroll
                for (int m = 0; m < 4; m++) {
                    unsigned long long zo = zr[2 * m + 1];
#pragma unroll
                    for (int i2 = 0; i2 < 9; i2++) fma2(B0[i2], pe[i2 + m], zo);
                }
            }
            // ---- phase 1 (oh = oh0 + 1) ----
            {
                const float* rp1 = rp + RST;
                unsigned long long pe[12];
#pragma unroll
                for (int q = 0; q < 6; q++) {
                    ulonglong2 v = *(const ulonglong2*)(rp1 + off[q]);
                    pe[2 * q] = v.x;
                    pe[2 * q + 1] = v.y;
                }
#pragma unroll
                for (int m = 0; m < 4; m++) {
                    unsigned long long ze = zr[2 * m];
#pragma unroll
                    for (int p = 0; p < 8; p++) fma2(A1[p], pe[p + m], ze);
                }
#pragma unroll
                for (int m = 0; m < 4; m++) {
                    unsigned long long zo = zr[2 * m + 1];
#pragma unroll
                    for (int i2 = 0; i2 < 9; i2++) fma2(B1[i2], pe[i2 + m], zo);
                }
            }
        }
    }

    int d = d0 + od;
    if (d >= 121) return;
    size_t dbase_o = ((size_t)(b * 121 + d)) * 121;

    {
        int h = h0 + oh0;
        if (h < 121) {
            float res[16];
#pragma unroll
            for (int p = 0; p < 8; p++) {
                float2 a = u2f(A0[p]);
                float2 bl = u2f(B0[p]);
                float2 br = u2f(B0[p + 1]);
                res[2 * p] = a.x + bl.y;
                res[2 * p + 1] = a.y + br.x;
            }
            size_t base = (dbase_o + h) * 121;
#pragma unroll
            for (int j = 0; j < 16; j++) {
                int w = wb + j;
                if (w < 121) out[base + w] = res[j] * __ldg(&g_dinv[base + w]);
            }
        }
    }
    {
        int h = h0 + oh0 + 1;
        if (h < 121) {
            float res[16];
#pragma unroll
            for (int p = 0; p < 8; p++) {
                float2 a = u2f(A1[p]);
                float2 bl = u2f(B1[p]);
                float2 br = u2f(B1[p + 1]);
                res[2 * p] = a.x + bl.y;
                res[2 * p + 1] = a.y + br.x;
            }
            size_t base = (dbase_o + h) * 121;
#pragma unroll
            for (int j = 0; j < 16; j++) {
                int w = wb + j;
                if (w < 121) out[base + w] = res[j] * __ldg(&g_dinv[base + w]);
            }
        }
    }
}

// ---------------------------------------------------------------------------
extern "C" void kernel_launch(void* const* d_in, const int* in_sizes, int n_in,
                              void* d_out, int out_size) {
    (void)n_in;
    (void)out_size;
    const float* z = (const float*)d_in[0];
    const float* x = (const float*)d_in[1];
    if (in_sizes[0] != NB * 512) {
        z = (const float*)d_in[1];
        x = (const float*)d_in[0];
    }
    float* out = (float*)d_out;

    cudaFuncSetAttribute(ncc_k_whsum,
                         cudaFuncAttributeMaxDynamicSharedMemorySize, WH_SMEM);
    cudaFuncSetAttribute(ncc_k_cross,
                         cudaFuncAttributeMaxDynamicSharedMemorySize, CR_SMEM);

    ncc_k_template<<<NB, 512>>>(z);
    ncc_k_whsum<<<NB * 128, 256, WH_SMEM>>>(x);
    ncc_k_dsum2<<<dim3(58, 4, NB), 256>>>();
    ncc_k_cross<<<dim3(16, 16, NB), 256, CR_SMEM>>>(x, out);
}